// round 2
// baseline (speedup 1.0000x reference)
#include <cuda_runtime.h>
#include <math_constants.h>
#include <stdint.h>

// MulticlassNMS: N=5000 boxes, C=81 classes (80 fg), conf=0.6, nms=0.5, top-300.
//
// Kernel A: one block per fg class. Compact valid (score>conf), bitonic sort
// descending by (score, idx) in shared, greedy NMS over a 1024-wide window of
// the sorted list (with exact extension fallback), stop after 300 keeps.
// Kernel B: single block; histogram-refine selection of global top-300 over
// the <=80*300 kept candidates, bitonic sort survivors, write preds+labels.

#define MAXN   5000
#define MAXCLS 128
#define MAXK   300
#define TA     256
#define TB     1024
#define WCHUNK 1024
#define GCAP   4096

__device__ float g_ks[MAXCLS * MAXK];
__device__ int   g_kb[MAXCLS * MAXK];
__device__ int   g_kc[MAXCLS];

// ---------------- Kernel A: per-class NMS ----------------
__global__ __launch_bounds__(TA)
void nms_class_kernel(const float* __restrict__ bboxes,
                      const float* __restrict__ scores,
                      const float* __restrict__ confp,
                      const float* __restrict__ nmsp,
                      int n, int c)
{
    extern __shared__ unsigned char smraw[];
    float4*        sbox = (float4*)smraw;                 // [5008]
    float*         skey = (float*)(sbox + 5008);          // [8192]
    int*           sidx = (int*)(skey + 8192);            // [8192]
    unsigned char* ssup = (unsigned char*)(sidx + 8192);  // [5008]

    __shared__ int    sM, sPtr, sJ, sKept;
    __shared__ int    skpos[MAXK];
    __shared__ float4 skbox;
    __shared__ float  skarea;

    const int   tid  = threadIdx.x;
    const int   cls  = blockIdx.x;          // fg class -> scores column cls+1
    const float conf = *confp;
    const float thr  = *nmsp;

    if (tid == 0) { sM = 0; sPtr = 0; sKept = 0; }
    __syncthreads();

    // compact valid candidates (order nondeterministic; sort canonicalizes)
    for (int i = tid; i < n; i += TA) {
        float s = scores[i * c + cls + 1];
        if (s > conf) {
            int p = atomicAdd(&sM, 1);
            skey[p] = s; sidx[p] = i;
        }
    }
    __syncthreads();
    const int M = sM;
    int P = 2; while (P < M) P <<= 1;
    for (int p = M + tid; p < P; p += TA) {
        skey[p] = -CUDART_INF_F; sidx[p] = -1;
    }
    __syncthreads();

    // bitonic sort, final order: descending by score, ties -> larger idx first
    for (int k = 2; k <= P; k <<= 1) {
        for (int j = k >> 1; j > 0; j >>= 1) {
            for (int p = tid; p < P; p += TA) {
                int q = p ^ j;
                if (q > p) {
                    float sa = skey[p], sb = skey[q];
                    int   ia = sidx[p], ib = sidx[q];
                    bool pLater = (sa < sb) || (sa == sb && ia < ib);
                    bool qLater = (sb < sa) || (sa == sb && ib < ia);
                    bool dirAsc = ((p & k) == 0);
                    if (dirAsc ? pLater : qLater) {
                        skey[p] = sb; skey[q] = sa;
                        sidx[p] = ib; sidx[q] = ia;
                    }
                }
            }
            __syncthreads();
        }
    }

    // gather candidate boxes into shared (bboxes rows are 16B-aligned float4)
    const float4* bb4 = (const float4*)bboxes;
    for (int p = tid; p < M; p += TA) sbox[p] = bb4[sidx[p]];
    for (int p = tid; p < M; p += TA) ssup[p] = 0;
    __syncthreads();

    int Wend = min(M, WCHUNK);
    for (;;) {
        if (tid == 0) {
            if (sKept >= MAXK) { sJ = -2; }
            else {
                int p2 = sPtr;
                while (p2 < Wend && ssup[p2]) p2++;
                if (p2 < Wend) {
                    sJ = p2;
                    float4 kb = sbox[p2];
                    skbox  = kb;
                    skarea = (kb.z - kb.x) * (kb.w - kb.y);
                    int kc = sKept;
                    skpos[kc] = p2;
                    g_ks[cls * MAXK + kc] = skey[p2];
                    g_kb[cls * MAXK + kc] = sidx[p2];
                    sKept = kc + 1;
                    sPtr  = p2 + 1;
                } else { sJ = -1; sPtr = p2; }
            }
        }
        __syncthreads();
        int j = sJ;
        if (j == -2) break;
        if (j == -1) {
            if (Wend >= M) break;
            // extend window: check new chunk against ALL kept so far (rare)
            int newEnd = min(M, Wend + WCHUNK);
            int kc = sKept;
            for (int p = Wend + tid; p < newEnd; p += TA) {
                float4 cb = sbox[p];
                float  ca = (cb.z - cb.x) * (cb.w - cb.y);
                unsigned char sup = 0;
                for (int kk = 0; kk < kc; kk++) {
                    float4 kb = sbox[skpos[kk]];
                    float  ka = (kb.z - kb.x) * (kb.w - kb.y);
                    float ix1 = fmaxf(kb.x, cb.x), iy1 = fmaxf(kb.y, cb.y);
                    float ix2 = fminf(kb.z, cb.z), iy2 = fminf(kb.w, cb.w);
                    float iw = fmaxf(ix2 - ix1, 0.f), ih = fmaxf(iy2 - iy1, 0.f);
                    float inter = iw * ih;
                    if (inter > 0.f) {
                        float u = (ka + ca) - inter;
                        if (__fdiv_rn(inter, u) > thr) { sup = 1; break; }
                    }
                }
                ssup[p] = sup;
            }
            Wend = newEnd;
            __syncthreads();
            continue;
        }
        // suppression sweep vs kept box j
        float4 kb = skbox;
        float  ka = skarea;
        for (int p = j + 1 + tid; p < Wend; p += TA) {
            if (!ssup[p]) {
                float4 cb = sbox[p];
                float ix1 = fmaxf(kb.x, cb.x), iy1 = fmaxf(kb.y, cb.y);
                float ix2 = fminf(kb.z, cb.z), iy2 = fminf(kb.w, cb.w);
                float iw = fmaxf(ix2 - ix1, 0.f), ih = fmaxf(iy2 - iy1, 0.f);
                float inter = iw * ih;
                if (inter > 0.f) {
                    float ca = (cb.z - cb.x) * (cb.w - cb.y);
                    float u  = (ka + ca) - inter;
                    if (__fdiv_rn(inter, u) > thr) ssup[p] = 1;
                }
            }
        }
        __syncthreads();
    }
    if (tid == 0) g_kc[cls] = sKept;
}

// ---------------- Kernel B: global top-300 + output ----------------
__global__ __launch_bounds__(TB)
void topk_kernel(const float* __restrict__ bboxes,
                 const float* __restrict__ confp,
                 float* __restrict__ out,
                 int n, int nc)
{
    __shared__ int hist[2048];
    __shared__ int schunk[256];
    __shared__ unsigned long long gkey[GCAP];
    __shared__ int   sTot, sGc, sDone, sAbove, smaxbits;
    __shared__ float sLo, sHi, sCut;

    const int tid = threadIdx.x;
    const int total_slots = nc * MAXK;

    if (tid == 0) { sTot = 0; sDone = 0; sAbove = 0; smaxbits = 0; sGc = 0; }
    __syncthreads();
    if (tid < nc) atomicAdd(&sTot, g_kc[tid]);

    // max score (all scores > conf > 0, so int-bit compare works)
    float m = -CUDART_INF_F;
    for (int s = tid; s < total_slots; s += TB) {
        int cc = s / MAXK, k = s - cc * MAXK;
        if (k < g_kc[cc]) m = fmaxf(m, g_ks[s]);
    }
    for (int o = 16; o; o >>= 1) m = fmaxf(m, __shfl_xor_sync(~0u, m, o));
    if ((tid & 31) == 0 && m > 0.f) atomicMax(&smaxbits, __float_as_int(m));
    __syncthreads();

    const int Tot = sTot;
    if (tid == 0) {
        sLo = *confp;
        sHi = __int_as_float(smaxbits) * 1.0000002f + 1e-30f;
        if (Tot <= MAXK) { sCut = -CUDART_INF_F; sDone = 1; }
    }
    __syncthreads();

    // histogram refinement to find cutoff so that <=GCAP survive
    for (int lev = 0; lev < 6; lev++) {
        if (sDone) break;
        for (int b = tid; b < 2048; b += TB) hist[b] = 0;
        __syncthreads();
        float L = sLo, H = sHi;
        float scale = 2048.0f / (H - L);
        for (int s = tid; s < total_slots; s += TB) {
            int cc = s / MAXK, k = s - cc * MAXK;
            if (k < g_kc[cc]) {
                float v = g_ks[s];
                if (v >= L && v < H) {
                    int bin = (int)((v - L) * scale);
                    bin = max(0, min(2047, bin));
                    atomicAdd(&hist[bin], 1);
                }
            }
        }
        __syncthreads();
        if (tid < 256) {
            int sum = 0;
            for (int b = tid * 8; b < tid * 8 + 8; b++) sum += hist[b];
            schunk[tid] = sum;
        }
        __syncthreads();
        if (tid == 0) {
            int acc = sAbove, bstar = -1;
            for (int ch = 255; ch >= 0 && bstar < 0; ch--) {
                if (acc + schunk[ch] < MAXK) { acc += schunk[ch]; }
                else {
                    for (int b = ch * 8 + 7; b >= ch * 8; b--) {
                        if (acc + hist[b] < MAXK) acc += hist[b];
                        else { bstar = b; break; }
                    }
                }
            }
            float w    = (H - L) / 2048.0f;
            float cutv = L + bstar * w;
            bool collapsed = !(w > 0.f) || (L + w == L);
            if (acc + hist[bstar] <= GCAP || lev == 5 || collapsed) {
                // nudge cutoff down 2 ulps so binning/rounding can't drop a
                // boundary element of bin bstar (slack absorbed by GCAP)
                float cut = cutv;
                if (cut > 0.f) cut = __uint_as_float(__float_as_uint(cut) - 2);
                sCut = cut; sDone = 1;
            } else {
                sAbove = acc;
                sLo = cutv;
                sHi = L + (bstar + 1) * w;
            }
        }
        __syncthreads();
    }

    // gather survivors
    const float cutoff = sCut;
    for (int s = tid; s < total_slots; s += TB) {
        int cc = s / MAXK, k = s - cc * MAXK;
        if (k < g_kc[cc]) {
            float v = g_ks[s];
            if (v >= cutoff) {
                int pos = atomicAdd(&sGc, 1);
                if (pos < GCAP) {
                    unsigned flat = (unsigned)(cc * n + g_kb[s]);
                    gkey[pos] = ((unsigned long long)__float_as_uint(v) << 32)
                                | (unsigned)(~flat);   // ties: lower flat first
                }
            }
        }
    }
    __syncthreads();
    const int G = min(sGc, GCAP);
    int P2 = 2; while (P2 < G) P2 <<= 1;
    for (int p = G + tid; p < P2; p += TB) gkey[p] = 0ULL;
    __syncthreads();

    // bitonic sort descending by raw 64-bit key
    for (int k = 2; k <= P2; k <<= 1) {
        for (int j = k >> 1; j > 0; j >>= 1) {
            for (int p = tid; p < P2; p += TB) {
                int q = p ^ j;
                if (q > p) {
                    unsigned long long a = gkey[p], b = gkey[q];
                    bool dirAsc = ((p & k) == 0);
                    if (dirAsc ? (a < b) : (a > b)) {
                        gkey[p] = b; gkey[q] = a;
                    }
                }
            }
            __syncthreads();
        }
    }

    // write outputs: preds [300,5] then labels [300] (as float)
    for (int i = tid; i < MAXK; i += TB) {
        bool valid = (i < G) && (gkey[i] != 0ULL);
        if (valid) {
            unsigned long long kk = gkey[i];
            float    s    = __uint_as_float((unsigned)(kk >> 32));
            unsigned flat = ~(unsigned)kk;
            int cc  = flat / n;
            int box = flat - cc * n;
            out[i * 5 + 0] = bboxes[box * 4 + 0];
            out[i * 5 + 1] = bboxes[box * 4 + 1];
            out[i * 5 + 2] = bboxes[box * 4 + 2];
            out[i * 5 + 3] = bboxes[box * 4 + 3];
            out[i * 5 + 4] = s;
            out[MAXK * 5 + i] = (float)(cc + 1);
        } else {
            out[i * 5 + 0] = 0.f; out[i * 5 + 1] = 0.f;
            out[i * 5 + 2] = 0.f; out[i * 5 + 3] = 0.f;
            out[i * 5 + 4] = 0.f;
            out[MAXK * 5 + i] = -1.0f;
        }
    }
}

// ---------------- launch ----------------
extern "C" void kernel_launch(void* const* d_in, const int* in_sizes, int n_in,
                              void* d_out, int out_size)
{
    const float* bboxes = (const float*)d_in[0];
    const float* scores = (const float*)d_in[1];
    const float* confp  = (const float*)d_in[2];
    const float* nmsp   = (const float*)d_in[3];

    int n = in_sizes[0] / 4;
    int c = in_sizes[1] / n;
    int nc = c - 1;

    static bool attr_set = false;
    const int smemA = 5008 * 16 + 8192 * 4 + 8192 * 4 + 5008;  // 150672 B
    if (!attr_set) {
        cudaFuncSetAttribute(nms_class_kernel,
                             cudaFuncAttributeMaxDynamicSharedMemorySize, smemA);
        attr_set = true;
    }

    nms_class_kernel<<<nc, TA, smemA>>>(bboxes, scores, confp, nmsp, n, c);
    topk_kernel<<<1, TB>>>(bboxes, confp, (float*)d_out, n, nc);
}

// round 5
// speedup vs baseline: 1.9461x; 1.9461x over previous
#include <cuda_runtime.h>
#include <math_constants.h>
#include <stdint.h>

// MulticlassNMS, chunked-greedy formulation.
// Kernel A (1 block/class): compact score>conf into 64-bit keys, fused bitonic
// sort (desc, ties->larger idx), then greedy NMS in 32-candidate chunks:
//   parallel chunk-vs-kept tests + ballot intra-chunk matrix + 1-thread
//   32-step bitmask resolve. Early stop at 300 keeps (safe for global top-300).
// Kernel B (1 block): histogram-refine global top-300 over <=80*300 keeps,
// fused bitonic sort of <=2048 survivors, write preds+labels.

#define MAXCLS 128
#define MAXK   300
#define TA     256
#define TB     256
#define SBOXN  1024
#define GCAP   2048

__device__ float g_ks[MAXCLS * MAXK];
__device__ int   g_kb[MAXCLS * MAXK];
__device__ int   g_kc[MAXCLS];

// exact IoU>thr predicate: multiply filter with __fdiv_rn fallback in the
// ~1e-4 boundary band (bit-exact vs reference's IEEE divide).
__device__ __forceinline__ bool iou_gt(const float4 a, float aa,
                                       const float4 b, float ba,
                                       float thr, float thrLo, float thrHi)
{
    float ix1 = fmaxf(a.x, b.x), iy1 = fmaxf(a.y, b.y);
    float ix2 = fminf(a.z, b.z), iy2 = fminf(a.w, b.w);
    float iw = ix2 - ix1, ih = iy2 - iy1;
    if (iw <= 0.f || ih <= 0.f) return false;
    float inter = iw * ih;
    float u = (aa + ba) - inter;
    if (inter > thrHi * u) return true;
    if (inter < thrLo * u) return false;
    return __fdiv_rn(inter, u) > thr;
}

// ---------------- Kernel A: per-class NMS ----------------
__global__ __launch_bounds__(TA)
void nms_class_kernel(const float4* __restrict__ bb4,
                      const float* __restrict__ scores,
                      const float* __restrict__ confp,
                      const float* __restrict__ nmsp,
                      int n, int c)
{
    extern __shared__ unsigned char smraw[];
    unsigned long long* skey  = (unsigned long long*)smraw;        // [8192]
    float4*             sbox  = (float4*)(skey + 8192);            // [SBOXN]
    float*              sarea = (float*)(sbox + SBOXN);            // [SBOXN]
    float4*             kbox  = (float4*)(sarea + SBOXN);          // [304]
    float*              karea = (float*)(kbox + 304);              // [304]
    float4*             cbox  = (float4*)(karea + 304);            // [32]
    float*              carea = (float*)(cbox + 32);               // [32]
    unsigned*           sIntra = (unsigned*)(carea + 32);          // [32]

    __shared__ int      sM, sKept;
    __shared__ unsigned sSupW, sKeptMask;

    const int tid  = threadIdx.x;
    const int wid  = tid >> 5, lane = tid & 31;
    const int cls  = blockIdx.x;                 // fg class -> column cls+1
    const float conf  = *confp;
    const float thr   = *nmsp;
    const float thrLo = thr * 0.9999f;
    const float thrHi = thr * 1.0001f;

    if (tid == 0) { sM = 0; sKept = 0; }
    __syncthreads();

    // compact valid candidates into 64-bit keys (score bits | idx);
    // scores > conf > 0 so float-bit order == value order.
    for (int i = tid; i < n; i += TA) {
        float s = scores[i * c + cls + 1];
        if (s > conf) {
            int p = atomicAdd(&sM, 1);
            skey[p] = ((unsigned long long)__float_as_uint(s) << 32) | (unsigned)i;
        }
    }
    __syncthreads();
    const int M = sM;
    int P = 8; while (P < M) P <<= 1;
    for (int p = M + tid; p < P; p += TA) skey[p] = 0ULL;
    __syncthreads();

    // bitonic sort descending; j<=4 stages fused in registers (8 elems/thread)
    for (int k = 2; k <= P; k <<= 1) {
        for (int j = k >> 1; j >= 8; j >>= 1) {
            for (int p = tid; p < P; p += TA) {
                int q = p ^ j;
                if (q > p) {
                    unsigned long long a = skey[p], b = skey[q];
                    bool dirDesc = ((p & k) == 0);
                    if (dirDesc ? (a < b) : (a > b)) { skey[p] = b; skey[q] = a; }
                }
            }
            __syncthreads();
        }
        int j0 = (k >> 1 < 4) ? (k >> 1) : 4;
        for (int base = tid * 8; base < P; base += TA * 8) {
            unsigned long long v[8];
            #pragma unroll
            for (int a2 = 0; a2 < 8; a2++) v[a2] = skey[base + a2];
            for (int j = j0; j > 0; j >>= 1) {
                #pragma unroll
                for (int a2 = 0; a2 < 8; a2++) {
                    int b2 = a2 ^ j;
                    if (b2 > a2) {
                        bool dirDesc = (((base + a2) & k) == 0);
                        unsigned long long x = v[a2], y = v[b2];
                        if (dirDesc ? (x < y) : (x > y)) { v[a2] = y; v[b2] = x; }
                    }
                }
            }
            #pragma unroll
            for (int a2 = 0; a2 < 8; a2++) skey[base + a2] = v[a2];
        }
        __syncthreads();
    }

    // prefetch top-SBOXN candidate boxes/areas into shared
    const int PF = min(M, SBOXN);
    for (int p = tid; p < PF; p += TA) {
        float4 b = bb4[(unsigned)(skey[p] & 0xffffffffu)];
        sbox[p]  = b;
        sarea[p] = (b.z - b.x) * (b.w - b.y);
    }
    __syncthreads();

    // chunked greedy NMS
    int pos = 0, nKept = 0;
    while (pos < M && nKept < MAXK) {
        // stage chunk (warp 0)
        if (wid == 0) {
            int cl2 = pos + lane;
            float4 cb;
            if (cl2 < M) {
                cb = (cl2 < PF) ? sbox[cl2]
                                : bb4[(unsigned)(skey[cl2] & 0xffffffffu)];
            } else cb = make_float4(0.f, 0.f, 0.f, 0.f);
            cbox[lane]  = cb;
            carea[lane] = (cb.z - cb.x) * (cb.w - cb.y);
            if (lane == 0) sSupW = 0;
        }
        __syncthreads();

        // all warps: chunk-vs-kept + intra-chunk matrix rows
        {
            float4 cb = cbox[lane];
            float  ca = carea[lane];
            bool sup = false;
            for (int k = wid; k < nKept; k += (TA / 32))
                sup |= iou_gt(kbox[k], karea[k], cb, ca, thr, thrLo, thrHi);
            unsigned w = __ballot_sync(0xffffffffu, sup);
            if (lane == 0 && w) atomicOr(&sSupW, w);

            #pragma unroll
            for (int r = 0; r < 4; r++) {
                int i = wid * 4 + r;
                float4 rb = cbox[i];
                float  ra = carea[i];
                bool pr = (lane > i) && iou_gt(rb, ra, cb, ca, thr, thrLo, thrHi);
                unsigned rw = __ballot_sync(0xffffffffu, pr);
                if (lane == 0) sIntra[i] = rw;
            }
        }
        __syncthreads();

        // single-thread bitmask resolve (registers only)
        if (tid == 0) {
            int nv = M - pos; if (nv > 32) nv = 32;
            unsigned validMask = (nv >= 32) ? 0xffffffffu : ((1u << nv) - 1u);
            unsigned suppressed = sSupW | ~validMask;
            unsigned keptM = 0;
            unsigned R[32];
            #pragma unroll
            for (int i2 = 0; i2 < 32; i2++) R[i2] = sIntra[i2];
            #pragma unroll
            for (int i2 = 0; i2 < 32; i2++) {
                if (!((suppressed >> i2) & 1u)) {
                    keptM |= (1u << i2);
                    suppressed |= R[i2];
                }
            }
            sKeptMask = keptM;
        }
        __syncthreads();

        // append keeps (warp 0)
        if (wid == 0) {
            unsigned keptM = sKeptMask;
            bool myKeep = (keptM >> lane) & 1u;
            int before  = __popc(keptM & ((1u << lane) - 1u));
            int myPos   = nKept + before;
            if (myKeep && myPos < MAXK) {
                kbox[myPos]  = cbox[lane];
                karea[myPos] = carea[lane];
                unsigned long long kk = skey[pos + lane];
                g_ks[cls * MAXK + myPos] = __uint_as_float((unsigned)(kk >> 32));
                g_kb[cls * MAXK + myPos] = (int)(unsigned)(kk & 0xffffffffu);
            }
            if (lane == 0) {
                int nk = nKept + __popc(keptM);
                sKept = (nk > MAXK) ? MAXK : nk;
            }
        }
        __syncthreads();
        nKept = sKept;
        pos  += 32;
    }
    if (tid == 0) g_kc[cls] = nKept;
}

// ---------------- Kernel B: global top-300 + output ----------------
__global__ __launch_bounds__(TB)
void topk_kernel(const float* __restrict__ bboxes,
                 const float* __restrict__ confp,
                 float* __restrict__ out,
                 int n, int nc)
{
    __shared__ int hist[2048];
    __shared__ int schunk[256];
    __shared__ unsigned long long gkey[GCAP];
    __shared__ int   sTot, sGc, sDone, sAbove, smaxbits;
    __shared__ float sLo, sHi, sCut;

    const int tid = threadIdx.x;
    const int total_slots = nc * MAXK;

    if (tid == 0) { sTot = 0; sDone = 0; sAbove = 0; smaxbits = 0; sGc = 0; }
    __syncthreads();
    if (tid < nc) atomicAdd(&sTot, g_kc[tid]);

    float m = 0.f;
    for (int s = tid; s < total_slots; s += TB) {
        int cc = s / MAXK, k = s - cc * MAXK;
        if (k < g_kc[cc]) m = fmaxf(m, g_ks[s]);
    }
    for (int o = 16; o; o >>= 1) m = fmaxf(m, __shfl_xor_sync(0xffffffffu, m, o));
    if ((tid & 31) == 0 && m > 0.f) atomicMax(&smaxbits, __float_as_int(m));
    __syncthreads();

    const int Tot = sTot;
    if (tid == 0) {
        sLo = *confp;
        sHi = __int_as_float(smaxbits) * 1.0000002f + 1e-30f;
        if (Tot <= MAXK) { sCut = -CUDART_INF_F; sDone = 1; }
    }
    __syncthreads();

    for (int lev = 0; lev < 8; lev++) {
        if (sDone) break;
        for (int b = tid; b < 2048; b += TB) hist[b] = 0;
        __syncthreads();
        float L = sLo, H = sHi;
        float scale = 2048.0f / (H - L);
        for (int s = tid; s < total_slots; s += TB) {
            int cc = s / MAXK, k = s - cc * MAXK;
            if (k < g_kc[cc]) {
                float v = g_ks[s];
                if (v >= L && v < H) {
                    int bin = (int)((v - L) * scale);
                    bin = max(0, min(2047, bin));
                    atomicAdd(&hist[bin], 1);
                }
            }
        }
        __syncthreads();
        if (tid < 256) {
            int sum = 0;
            for (int b = tid * 8; b < tid * 8 + 8; b++) sum += hist[b];
            schunk[tid] = sum;
        }
        __syncthreads();
        if (tid == 0) {
            int acc = sAbove, bstar = -1;
            for (int ch = 255; ch >= 0 && bstar < 0; ch--) {
                if (acc + schunk[ch] < MAXK) { acc += schunk[ch]; }
                else {
                    for (int b = ch * 8 + 7; b >= ch * 8; b--) {
                        if (acc + hist[b] < MAXK) acc += hist[b];
                        else { bstar = b; break; }
                    }
                }
            }
            float w    = (H - L) / 2048.0f;
            float cutv = L + bstar * w;
            bool collapsed = !(w > 0.f) || (L + w == L);
            if (acc + hist[bstar] <= GCAP || lev == 7 || collapsed) {
                float cut = cutv;
                if (cut > 0.f) cut = __uint_as_float(__float_as_uint(cut) - 2);
                sCut = cut; sDone = 1;
            } else {
                sAbove = acc;
                sLo = cutv;
                sHi = L + (bstar + 1) * w;
            }
        }
        __syncthreads();
    }

    // gather survivors
    const float cutoff = sCut;
    for (int s = tid; s < total_slots; s += TB) {
        int cc = s / MAXK, k = s - cc * MAXK;
        if (k < g_kc[cc]) {
            float v = g_ks[s];
            if (v >= cutoff) {
                int pos = atomicAdd(&sGc, 1);
                if (pos < GCAP) {
                    unsigned flat = (unsigned)(cc * n + g_kb[s]);
                    gkey[pos] = ((unsigned long long)__float_as_uint(v) << 32)
                                | (unsigned)(~flat);   // ties: lower flat first
                }
            }
        }
    }
    __syncthreads();
    const int G = min(sGc, GCAP);
    for (int p = G + tid; p < GCAP; p += TB) gkey[p] = 0ULL;
    __syncthreads();

    // fused bitonic sort, fixed P=2048, 8 elems/thread local stages
    const int P = GCAP;
    for (int k = 2; k <= P; k <<= 1) {
        for (int j = k >> 1; j >= 8; j >>= 1) {
            for (int p = tid; p < P; p += TB) {
                int q = p ^ j;
                if (q > p) {
                    unsigned long long a = gkey[p], b = gkey[q];
                    bool dirDesc = ((p & k) == 0);
                    if (dirDesc ? (a < b) : (a > b)) { gkey[p] = b; gkey[q] = a; }
                }
            }
            __syncthreads();
        }
        int j0 = (k >> 1 < 4) ? (k >> 1) : 4;
        {
            int base = tid * 8;
            unsigned long long v[8];
            #pragma unroll
            for (int a2 = 0; a2 < 8; a2++) v[a2] = gkey[base + a2];
            for (int j = j0; j > 0; j >>= 1) {
                #pragma unroll
                for (int a2 = 0; a2 < 8; a2++) {
                    int b2 = a2 ^ j;
                    if (b2 > a2) {
                        bool dirDesc = (((base + a2) & k) == 0);
                        unsigned long long x = v[a2], y = v[b2];
                        if (dirDesc ? (x < y) : (x > y)) { v[a2] = y; v[b2] = x; }
                    }
                }
            }
            #pragma unroll
            for (int a2 = 0; a2 < 8; a2++) gkey[base + a2] = v[a2];
        }
        __syncthreads();
    }

    // outputs: preds [300,5] then labels [300] (as float)
    for (int i = tid; i < MAXK; i += TB) {
        bool valid = (i < G) && (gkey[i] != 0ULL);
        if (valid) {
            unsigned long long kk = gkey[i];
            float    s    = __uint_as_float((unsigned)(kk >> 32));
            unsigned flat = ~(unsigned)kk;
            int cc  = flat / n;
            int box = flat - cc * n;
            out[i * 5 + 0] = bboxes[box * 4 + 0];
            out[i * 5 + 1] = bboxes[box * 4 + 1];
            out[i * 5 + 2] = bboxes[box * 4 + 2];
            out[i * 5 + 3] = bboxes[box * 4 + 3];
            out[i * 5 + 4] = s;
            out[MAXK * 5 + i] = (float)(cc + 1);
        } else {
            out[i * 5 + 0] = 0.f; out[i * 5 + 1] = 0.f;
            out[i * 5 + 2] = 0.f; out[i * 5 + 3] = 0.f;
            out[i * 5 + 4] = 0.f;
            out[MAXK * 5 + i] = -1.0f;
        }
    }
}

// ---------------- launch ----------------
extern "C" void kernel_launch(void* const* d_in, const int* in_sizes, int n_in,
                              void* d_out, int out_size)
{
    const float* bboxes = (const float*)d_in[0];
    const float* scores = (const float*)d_in[1];
    const float* confp  = (const float*)d_in[2];
    const float* nmsp   = (const float*)d_in[3];

    int n  = in_sizes[0] / 4;
    int c  = in_sizes[1] / n;
    int nc = c - 1;

    const int smemA = 8192 * 8 + SBOXN * 16 + SBOXN * 4
                    + 304 * 16 + 304 * 4 + 32 * 16 + 32 * 4 + 32 * 4; // 92864
    static bool attr_set = false;
    if (!attr_set) {
        cudaFuncSetAttribute(nms_class_kernel,
                             cudaFuncAttributeMaxDynamicSharedMemorySize, smemA);
        attr_set = true;
    }

    nms_class_kernel<<<nc, TA, smemA>>>((const float4*)bboxes, scores,
                                        confp, nmsp, n, c);
    topk_kernel<<<1, TB>>>(bboxes, confp, (float*)d_out, n, nc);
}

// round 7
// speedup vs baseline: 3.5597x; 1.8291x over previous
#include <cuda_runtime.h>
#include <math_constants.h>
#include <stdint.h>

// MulticlassNMS, chunked-greedy formulation v3.
// Kernel A (1 block/class, 512 thr): ballot-compact score>conf into 64-bit
// keys, fused bitonic sort, greedy NMS in 64-candidate chunks with
// sparse-row resolve (only nonzero suppression rows walked serially).
// Kernel B (1 block, 1024 thr): shared-resident histogram-refine top-300 over
// zero-padded 80*300 keeps, sort <=512 survivors, write preds+labels.

#define MAXCLS 128
#define MAXK   300
#define TA     512
#define TB     1024
#define SBOXN  1024
#define GCAP   512

__device__ float g_ks[MAXCLS * MAXK];
__device__ int   g_kb[MAXCLS * MAXK];
__device__ int   g_kc[MAXCLS];

// exact IoU>thr predicate: multiply filter, __fdiv_rn fallback in the ~1e-4
// boundary band (bit-exact vs reference's IEEE divide).
__device__ __forceinline__ bool iou_gt(const float4 a, float aa,
                                       const float4 b, float ba,
                                       float thr, float thrLo, float thrHi)
{
    float ix1 = fmaxf(a.x, b.x), iy1 = fmaxf(a.y, b.y);
    float ix2 = fminf(a.z, b.z), iy2 = fminf(a.w, b.w);
    float iw = ix2 - ix1, ih = iy2 - iy1;
    if (iw <= 0.f || ih <= 0.f) return false;
    float inter = iw * ih;
    float u = (aa + ba) - inter;
    if (inter > thrHi * u) return true;
    if (inter < thrLo * u) return false;
    return __fdiv_rn(inter, u) > thr;
}

// ---------------- Kernel A: per-class NMS ----------------
__global__ __launch_bounds__(TA)
void nms_class_kernel(const float4* __restrict__ bb4,
                      const float* __restrict__ scores,
                      const float* __restrict__ confp,
                      const float* __restrict__ nmsp,
                      int n, int c)
{
    extern __shared__ unsigned char smraw[];
    float4*             sbox   = (float4*)smraw;                    // [1024]
    float4*             kbox   = (float4*)(smraw + 16384);          // [304]
    float4*             cbox   = (float4*)(smraw + 21248);          // [64]
    unsigned long long* skey   = (unsigned long long*)(smraw + 22272); // [8192]
    float*              sarea  = (float*)(smraw + 87808);           // [1024]
    float*              karea  = (float*)(smraw + 91904);           // [304]
    float*              carea  = (float*)(smraw + 93120);           // [64]
    unsigned*           sIntra = (unsigned*)(smraw + 93376);        // [128]
    unsigned*           snzw   = (unsigned*)(smraw + 93888);        // [16]
    unsigned*           sSup32 = (unsigned*)(smraw + 93952);        // [2]

    __shared__ int sM;
    __shared__ unsigned long long sKeptMask;

    const int tid  = threadIdx.x;
    const int wid  = tid >> 5, lane = tid & 31;
    const int cls  = blockIdx.x;                 // fg class -> column cls+1
    const float conf  = *confp;
    const float thr   = *nmsp;
    const float thrLo = thr * 0.9999f;
    const float thrHi = thr * 1.0001f;
    const unsigned FULL = 0xffffffffu;

    if (tid == 0) sM = 0;
    __syncthreads();

    // ---- ballot-aggregated compaction into 64-bit keys (score|idx) ----
    const int nR = ((n + TA - 1) / TA) * TA;
    for (int i = tid; i < nR; i += TA) {
        bool v = false; float s = 0.f;
        if (i < n) { s = scores[i * c + cls + 1]; v = (s > conf); }
        unsigned bm = __ballot_sync(FULL, v);
        int base = 0;
        if (lane == 0 && bm) base = atomicAdd(&sM, __popc(bm));
        base = __shfl_sync(FULL, base, 0);
        if (v) {
            int p = base + __popc(bm & ((1u << lane) - 1u));
            skey[p] = ((unsigned long long)__float_as_uint(s) << 32) | (unsigned)i;
        }
    }
    __syncthreads();
    const int M = sM;
    int P = 8; while (P < M) P <<= 1;
    for (int p = M + tid; p < P; p += TA) skey[p] = 0ULL;
    __syncthreads();

    // ---- bitonic sort desc (ties -> larger idx); j<=4 fused in registers ----
    for (int k = 2; k <= P; k <<= 1) {
        for (int j = k >> 1; j >= 8; j >>= 1) {
            for (int p = tid; p < P; p += TA) {
                int q = p ^ j;
                if (q > p) {
                    unsigned long long a = skey[p], b = skey[q];
                    bool dirDesc = ((p & k) == 0);
                    if (dirDesc ? (a < b) : (a > b)) { skey[p] = b; skey[q] = a; }
                }
            }
            __syncthreads();
        }
        int j0 = (k >> 1 < 4) ? (k >> 1) : 4;
        for (int base = tid * 8; base < P; base += TA * 8) {
            unsigned long long v[8];
            #pragma unroll
            for (int a2 = 0; a2 < 8; a2++) v[a2] = skey[base + a2];
            for (int j = j0; j > 0; j >>= 1) {
                #pragma unroll
                for (int a2 = 0; a2 < 8; a2++) {
                    int b2 = a2 ^ j;
                    if (b2 > a2) {
                        bool dirDesc = (((base + a2) & k) == 0);
                        unsigned long long x = v[a2], y = v[b2];
                        if (dirDesc ? (x < y) : (x > y)) { v[a2] = y; v[b2] = x; }
                    }
                }
            }
            #pragma unroll
            for (int a2 = 0; a2 < 8; a2++) skey[base + a2] = v[a2];
        }
        __syncthreads();
    }

    // ---- prefetch top candidates' boxes/areas ----
    const int PF = min(M, SBOXN);
    for (int p = tid; p < PF; p += TA) {
        float4 b = bb4[(unsigned)(skey[p] & 0xffffffffu)];
        sbox[p]  = b;
        sarea[p] = (b.z - b.x) * (b.w - b.y);
    }
    __syncthreads();

    // ---- chunked greedy NMS, 64-wide chunks ----
    int pos = 0, nKept = 0;
    while (pos < M && nKept < MAXK) {
        const int nv = min(64, M - pos);

        // stage chunk + clear flags
        if (tid < 64) {
            int cl2 = pos + tid;
            float4 cb = make_float4(0.f, 0.f, 0.f, 0.f);
            if (cl2 < M)
                cb = (cl2 < PF) ? sbox[cl2]
                                : bb4[(unsigned)(skey[cl2] & 0xffffffffu)];
            cbox[tid]  = cb;
            carea[tid] = (cb.z - cb.x) * (cb.w - cb.y);
            if (tid < 2)  sSup32[tid] = 0;
            if (tid < 16) snzw[tid]   = 0;
        }
        __syncthreads();

        // work: chunk-vs-kept + intra-chunk ballot matrix (rows x 2 words)
        {
            // vs-kept: warp w covers candidate group (w&1), k stride 8
            int cg = wid & 1;
            int cc = (cg << 5) | lane;
            float4 cb = cbox[cc];
            float  ca = carea[cc];
            bool sup = false;
            for (int k = wid >> 1; k < nKept; k += 8)
                sup |= iou_gt(kbox[k], karea[k], cb, ca, thr, thrLo, thrHi);
            unsigned bm = __ballot_sync(FULL, sup);
            if (lane == 0 && bm) atomicOr(&sSup32[cg], bm);

            // intra: warp w owns rows 4w..4w+3
            unsigned nzm = 0;
            #pragma unroll
            for (int r0 = 0; r0 < 4; r0++) {
                int r = (wid << 2) + r0;
                float4 rb = cbox[r];
                float  ra = carea[r];
                #pragma unroll
                for (int g = 0; g < 2; g++) {
                    int col = (g << 5) | lane;
                    bool pr = (col > r) &&
                              iou_gt(rb, ra, cbox[col], carea[col], thr, thrLo, thrHi);
                    unsigned w2 = __ballot_sync(FULL, pr);
                    if (lane == 0) {
                        sIntra[r * 2 + g] = w2;
                        if (w2) nzm |= 1u << (r0 * 2 + g);
                    }
                }
            }
            if (lane == 0) snzw[wid] = nzm;
        }
        __syncthreads();

        // sparse greedy resolve (thread 0): walk only nonzero rows
        if (tid == 0) {
            unsigned long long valid = (nv >= 64) ? ~0ULL : ((1ULL << nv) - 1ULL);
            unsigned long long sup = (((unsigned long long)sSup32[1] << 32) |
                                       sSup32[0]) | ~valid;
            unsigned long long nz = 0;
            #pragma unroll
            for (int w = 0; w < 16; w++) {
                unsigned m = snzw[w];
                unsigned rowbits = 0;
                #pragma unroll
                for (int r0 = 0; r0 < 4; r0++)
                    if (m & (3u << (2 * r0))) rowbits |= 1u << r0;
                nz |= (unsigned long long)rowbits << (4 * w);
            }
            unsigned long long kept = 0;
            int prev = 0;
            while (nz) {
                int i = __ffsll((long long)nz) - 1;
                nz &= nz - 1;
                unsigned long long upto  = (i >= 63) ? ~0ULL : ((1ULL << (i + 1)) - 1ULL);
                unsigned long long fromp = (~0ULL) << prev;   // prev <= 63 here
                kept |= ~sup & upto & fromp;
                if (!((sup >> i) & 1ULL)) {
                    unsigned long long row =
                        (((unsigned long long)sIntra[2 * i + 1]) << 32) | sIntra[2 * i];
                    sup |= row;
                }
                prev = i + 1;
            }
            unsigned long long fromp = (prev >= 64) ? 0ULL : ((~0ULL) << prev);
            kept |= ~sup & fromp;
            sKeptMask = kept & valid;
        }
        __syncthreads();

        // append keeps (no barrier after: next stage's barrier orders kbox)
        unsigned long long kept = sKeptMask;
        if (tid < 64) {
            bool mk = (kept >> tid) & 1ULL;
            int before = __popcll(kept & ((1ULL << tid) - 1ULL));
            int myPos  = nKept + before;
            if (mk && myPos < MAXK) {
                kbox[myPos]  = cbox[tid];
                karea[myPos] = carea[tid];
                unsigned long long kk = skey[pos + tid];
                g_ks[cls * MAXK + myPos] = __uint_as_float((unsigned)(kk >> 32));
                g_kb[cls * MAXK + myPos] = (int)(unsigned)(kk & 0xffffffffu);
            }
        }
        int nk = nKept + __popcll(kept);
        nKept = (nk > MAXK) ? MAXK : nk;
        pos  += 64;
    }

    // zero-pad score tail so kernel B needs no per-class counts
    for (int p = nKept + tid; p < MAXK; p += TA) g_ks[cls * MAXK + p] = 0.f;
    if (tid == 0) g_kc[cls] = nKept;
}

// ---------------- Kernel B: global top-300 + output ----------------
__global__ __launch_bounds__(TB)
void topk_kernel(const float* __restrict__ bboxes,
                 const float* __restrict__ confp,
                 float* __restrict__ out,
                 int n, int nc)
{
    extern __shared__ unsigned char smrawB[];
    unsigned long long* gkey   = (unsigned long long*)smrawB;      // [512]
    float*              sval   = (float*)(smrawB + 4096);          // [24000]
    int*                hist   = (int*)(smrawB + 100096);          // [2048]
    int*                schunk = (int*)(smrawB + 108288);          // [256]

    __shared__ int   sTot, sGc, sDone, sAbove, smaxbits;
    __shared__ float sLo, sHi, sCut;

    const int tid = threadIdx.x;
    const int total_slots = nc * MAXK;
    const float conf = *confp;

    if (tid == 0) { sTot = 0; sDone = 0; sAbove = 0; smaxbits = 0; sGc = 0; }
    __syncthreads();
    if (tid < nc) atomicAdd(&sTot, g_kc[tid]);

    // stage scores into shared, fused max
    float m = 0.f;
    for (int s = tid; s < total_slots; s += TB) {
        float v = g_ks[s];
        sval[s] = v;
        m = fmaxf(m, v);
    }
    for (int o = 16; o; o >>= 1) m = fmaxf(m, __shfl_xor_sync(0xffffffffu, m, o));
    if ((tid & 31) == 0 && m > 0.f) atomicMax(&smaxbits, __float_as_int(m));
    __syncthreads();

    if (tid == 0) {
        sLo = conf;
        sHi = __int_as_float(smaxbits) * 1.0000002f + 1e-30f;
        if (sTot <= MAXK) { sCut = 0.f; sDone = 1; }
    }
    __syncthreads();

    // histogram refinement from shared-resident values
    for (int lev = 0; lev < 6; lev++) {
        if (sDone) break;
        for (int b = tid; b < 2048; b += TB) hist[b] = 0;
        __syncthreads();
        float L = sLo, H = sHi;
        float scale = 2048.0f / (H - L);
        for (int s = tid; s < total_slots; s += TB) {
            float v = sval[s];
            if (v > conf && v >= L && v < H) {
                int bin = (int)((v - L) * scale);
                bin = max(0, min(2047, bin));
                atomicAdd(&hist[bin], 1);
            }
        }
        __syncthreads();
        if (tid < 256) {
            int sum = 0;
            for (int b = tid * 8; b < tid * 8 + 8; b++) sum += hist[b];
            schunk[tid] = sum;
        }
        __syncthreads();
        if (tid == 0) {
            int acc = sAbove, bstar = -1;
            for (int ch = 255; ch >= 0 && bstar < 0; ch--) {
                if (acc + schunk[ch] < MAXK) { acc += schunk[ch]; }
                else {
                    for (int b = ch * 8 + 7; b >= ch * 8; b--) {
                        if (acc + hist[b] < MAXK) acc += hist[b];
                        else { bstar = b; break; }
                    }
                }
            }
            float w    = (H - L) / 2048.0f;
            float cutv = L + bstar * w;
            bool collapsed = !(w > 0.f) || (L + w == L);
            if (acc + hist[bstar] <= GCAP || lev == 5 || collapsed) {
                float cut = cutv;
                if (cut > 0.f) cut = __uint_as_float(__float_as_uint(cut) - 2);
                sCut = cut; sDone = 1;
            } else {
                sAbove = acc;
                sLo = cutv;
                sHi = L + (bstar + 1) * w;
            }
        }
        __syncthreads();
    }

    // gather survivors (score > conf excludes zero padding)
    const float cutoff = sCut;
    for (int s = tid; s < total_slots; s += TB) {
        float v = sval[s];
        if (v > conf && v >= cutoff) {
            int pos = atomicAdd(&sGc, 1);
            if (pos < GCAP) {
                int cc = s / MAXK;
                unsigned flat = (unsigned)(cc * n + g_kb[s]);
                gkey[pos] = ((unsigned long long)__float_as_uint(v) << 32)
                            | (unsigned)(~flat);   // ties: lower flat first
            }
        }
    }
    __syncthreads();
    const int G = min(sGc, GCAP);
    for (int p = G + tid; p < GCAP; p += TB) gkey[p] = 0ULL;
    __syncthreads();

    // bitonic sort desc, fixed P=512, j<=4 fused in registers
    const int P = GCAP;
    for (int k = 2; k <= P; k <<= 1) {
        for (int j = k >> 1; j >= 8; j >>= 1) {
            for (int p = tid; p < P; p += TB) {
                int q = p ^ j;
                if (q > p) {
                    unsigned long long a = gkey[p], b = gkey[q];
                    bool dirDesc = ((p & k) == 0);
                    if (dirDesc ? (a < b) : (a > b)) { gkey[p] = b; gkey[q] = a; }
                }
            }
            __syncthreads();
        }
        int j0 = (k >> 1 < 4) ? (k >> 1) : 4;
        {
            int base = tid * 8;
            if (base < P) {
                unsigned long long v[8];
                #pragma unroll
                for (int a2 = 0; a2 < 8; a2++) v[a2] = gkey[base + a2];
                for (int j = j0; j > 0; j >>= 1) {
                    #pragma unroll
                    for (int a2 = 0; a2 < 8; a2++) {
                        int b2 = a2 ^ j;
                        if (b2 > a2) {
                            bool dirDesc = (((base + a2) & k) == 0);
                            unsigned long long x = v[a2], y = v[b2];
                            if (dirDesc ? (x < y) : (x > y)) { v[a2] = y; v[b2] = x; }
                        }
                    }
                }
                #pragma unroll
                for (int a2 = 0; a2 < 8; a2++) gkey[base + a2] = v[a2];
            }
        }
        __syncthreads();
    }

    // outputs: preds [300,5] then labels [300] (as float)
    for (int i = tid; i < MAXK; i += TB) {
        bool valid = (i < G) && (gkey[i] != 0ULL);
        if (valid) {
            unsigned long long kk = gkey[i];
            float    s    = __uint_as_float((unsigned)(kk >> 32));
            unsigned flat = ~(unsigned)kk;
            int cc  = flat / n;
            int box = flat - cc * n;
            out[i * 5 + 0] = bboxes[box * 4 + 0];
            out[i * 5 + 1] = bboxes[box * 4 + 1];
            out[i * 5 + 2] = bboxes[box * 4 + 2];
            out[i * 5 + 3] = bboxes[box * 4 + 3];
            out[i * 5 + 4] = s;
            out[MAXK * 5 + i] = (float)(cc + 1);
        } else {
            out[i * 5 + 0] = 0.f; out[i * 5 + 1] = 0.f;
            out[i * 5 + 2] = 0.f; out[i * 5 + 3] = 0.f;
            out[i * 5 + 4] = 0.f;
            out[MAXK * 5 + i] = -1.0f;
        }
    }
}

// ---------------- launch ----------------
extern "C" void kernel_launch(void* const* d_in, const int* in_sizes, int n_in,
                              void* d_out, int out_size)
{
    const float* bboxes = (const float*)d_in[0];
    const float* scores = (const float*)d_in[1];
    const float* confp  = (const float*)d_in[2];
    const float* nmsp   = (const float*)d_in[3];

    int n  = in_sizes[0] / 4;
    int c  = in_sizes[1] / n;
    int nc = c - 1;

    const int smemA = 94208;
    const int smemB = 110080;
    static bool attr_set = false;
    if (!attr_set) {
        cudaFuncSetAttribute(nms_class_kernel,
                             cudaFuncAttributeMaxDynamicSharedMemorySize, smemA);
        cudaFuncSetAttribute(topk_kernel,
                             cudaFuncAttributeMaxDynamicSharedMemorySize, smemB);
        attr_set = true;
    }

    nms_class_kernel<<<nc, TA, smemA>>>((const float4*)bboxes, scores,
                                        confp, nmsp, n, c);
    topk_kernel<<<1, TB, smemB>>>(bboxes, confp, (float*)d_out, n, nc);
}